// round 12
// baseline (speedup 1.0000x reference)
#include <cuda_runtime.h>
#include <cuda_fp16.h>
#include <cstdint>
#include <cstddef>

// ============================================================================
// Problem constants
// ============================================================================
#define M_TOTAL 8192
#define N_TOTAL 4096
#define K_TOTAL 4096

#define TILE_M 128
#define TILE_N 128
#define TILE_K 64            // fp16 elems per stage row-chunk (128 bytes)
#define STAGES 3             // 96KB -> two CTAs per SM
#define NITER (K_TOTAL / TILE_K)   // 64

#define A_STAGE_BYTES (TILE_M * 128)          // 16384
#define B_STAGE_BYTES (TILE_N * 128)          // 16384
#define STAGE_BYTES (A_STAGE_BYTES + B_STAGE_BYTES)   // 32768
#define SMEM_TOTAL (STAGES * STAGE_BYTES)             // 98304

// Producer CTAs: 64 dedicated conversion CTAs, 16 units each, chunk-major.
#define PRE_CTAS 64
#define UNITS_PER_CHUNK 16

// ============================================================================
// Device scratch (allocation-free: __device__ globals)
// ============================================================================
__device__ __half g_xh[(size_t)M_TOTAL * K_TOTAL];   // 64 MB  x in fp16, [M,K]
__device__ __half g_wh[(size_t)N_TOTAL * K_TOTAL];   // 32 MB  unpacked q in fp16, [N,K]
__device__ float  g_bias[N_TOTAL];
__device__ int    g_done[NITER];                     // per-chunk completion counters

// ============================================================================
// PTX helpers (baseline sm_103 target — NO 'a'-suffix features)
// ============================================================================
__device__ __forceinline__ uint32_t smem_u32(const void* p) {
    uint32_t a;
    asm("{ .reg .u64 t; cvta.to.shared.u64 t, %1; cvt.u32.u64 %0, t; }" : "=r"(a) : "l"(p));
    return a;
}

__device__ __forceinline__ int ld_acquire(const int* p) {
    int v;
    asm volatile("ld.acquire.gpu.global.b32 %0, [%1];" : "=r"(v) : "l"(p) : "memory");
    return v;
}
__device__ __forceinline__ void red_release_add1(int* p) {
    asm volatile("red.release.gpu.global.add.s32 [%0], 1;" :: "l"(p) : "memory");
}

#define CP_ASYNC16(smem, gmem) \
    asm volatile("cp.async.cg.shared.global [%0], [%1], 16;" \
                 :: "r"(smem), "l"(gmem) : "memory")
#define CP_COMMIT() asm volatile("cp.async.commit_group;" ::: "memory")
#define CP_WAIT()   asm volatile("cp.async.wait_group %0;" :: "n"(STAGES - 2) : "memory")

#define LDMATRIX_X4(r0, r1, r2, r3, addr) \
    asm volatile("ldmatrix.sync.aligned.m8n8.x4.shared.b16 {%0,%1,%2,%3}, [%4];" \
                 : "=r"(r0), "=r"(r1), "=r"(r2), "=r"(r3) : "r"(addr))

__device__ __forceinline__ void mma16816(float* c, const uint32_t* a, const uint32_t* b) {
    asm volatile(
        "mma.sync.aligned.m16n8k16.row.col.f32.f16.f16.f32 "
        "{%0,%1,%2,%3}, {%4,%5,%6,%7}, {%8,%9}, {%0,%1,%2,%3};"
        : "+f"(c[0]), "+f"(c[1]), "+f"(c[2]), "+f"(c[3])
        : "r"(a[0]), "r"(a[1]), "r"(a[2]), "r"(a[3]), "r"(b[0]), "r"(b[1]));
}

// ============================================================================
// Fused kernel: bids [0, PRE_CTAS) = producers (conversion), rest = GEMM.
// ============================================================================
__global__ void __launch_bounds__(256, 2) fused_kernel(
    float* __restrict__ out,
    const float* __restrict__ x,
    const int* __restrict__ pw,
    const int* __restrict__ pb,
    const float* __restrict__ scale_w_p,
    const float* __restrict__ scale_b_p)
{
    const int tid = threadIdx.x;

    // ------------------------------------------------------------------
    // Producer branch: 16 units, stride-PRE_CTAS (chunk-major completion).
    // unit t: chunk c = t>>4, part u = t&15.
    //   u<8 : x rows [1024u, +1024), float4 cols [16c, +16)  (fp32 -> fp16)
    //   u>=8: w rows [512(u-8), +512), int32 cols [32c, +32) (int4 -> fp16)
    // ------------------------------------------------------------------
    if (blockIdx.x < PRE_CTAS) {
        const int bid = blockIdx.x;
        const float4* xv = reinterpret_cast<const float4*>(x);
        #pragma unroll 1
        for (int k = 0; k < 16; k++) {
            const int t = bid + (k << 6);     // 0..1023
            const int c = t >> 4;
            const int u = t & 15;
            if (u < 8) {
                const int row0 = u << 10;
                #pragma unroll 8
                for (int j = 0; j < 64; j++) {
                    const int idx = j * 256 + tid;
                    const int row = row0 + (idx >> 4);
                    const int f4  = idx & 15;
                    float4 v = xv[(size_t)row * 1024 + (c << 4) + f4];
                    __half2 h0 = __floats2half2_rn(v.x, v.y);
                    __half2 h1 = __floats2half2_rn(v.z, v.w);
                    uint2 pk;
                    pk.x = *reinterpret_cast<unsigned*>(&h0);
                    pk.y = *reinterpret_cast<unsigned*>(&h1);
                    reinterpret_cast<uint2*>(g_xh)[(size_t)row * 1024 + (c << 4) + f4] = pk;
                }
            } else {
                const int row0 = (u - 8) << 9;
                #pragma unroll 8
                for (int j = 0; j < 64; j++) {
                    const int idx = j * 256 + tid;
                    const int row = row0 + (idx >> 5);
                    const int q   = idx & 31;
                    const int b = pw[(size_t)row * 2048 + (c << 5) + q];
                    const int hi = ((b >> 4) & 15) - 8;
                    const int lo = (b & 15) - 8;
                    reinterpret_cast<__half2*>(g_wh)[(size_t)row * 2048 + (c << 5) + q] =
                        __halves2half2(__int2half_rn(hi), __int2half_rn(lo));
                }
                if (t == 15) {   // bias rides on chunk-0 unit 15
                    const float sbv = *scale_b_p;
                    for (int i = tid; i < N_TOTAL / 2; i += 256) {
                        const int bb = pb[i];
                        g_bias[2 * i]     = sbv * (float)(((bb >> 4) & 15) - 8);
                        g_bias[2 * i + 1] = sbv * (float)((bb & 15) - 8);
                    }
                }
            }
            __syncthreads();                  // all threads finished this unit
            if (tid == 0) red_release_add1(&g_done[c]);
        }
        return;
    }

    // ------------------------------------------------------------------
    // GEMM branch (round-9 structure + pipelined acquire gate)
    // ------------------------------------------------------------------
    extern __shared__ __align__(1024) char smem[];
    const uint32_t sb = smem_u32(smem);

    const int gbid = blockIdx.x - PRE_CTAS;
    const int wid = tid >> 5;
    const int lid = tid & 31;
    const int warp_m = wid & 1;   // 0..1
    const int warp_n = wid >> 1;  // 0..3

    const int m0 = (gbid >> 5) * TILE_M;
    const int n0 = (gbid & 31) * TILE_N;

    const int ld_row = tid >> 3;          // 0..31 row-subgroup
    const int ld_chk = tid & 7;           // 0..7  16B column chunk
    const __half* gA = g_xh + (size_t)(m0 + ld_row) * K_TOTAL + ld_chk * 8;
    const __half* gB = g_wh + (size_t)(n0 + ld_row) * K_TOTAL + ld_chk * 8;
    const uint32_t sw_off = (uint32_t)((ld_chk ^ (ld_row & 7)) << 4);

    const int s7 = lid & 7;
    const int q  = lid >> 3;
    const int a_row = warp_m * 64 + ((q & 1) << 3) + s7;
    const int kc_a = q >> 1;
    const int b_row = warp_n * 32 + ((q >> 1) << 3) + s7;
    const int kc_b = q & 1;

    float acc[4][4][4];
    #pragma unroll
    for (int mt = 0; mt < 4; mt++)
        #pragma unroll
        for (int nt = 0; nt < 4; nt++)
            #pragma unroll
            for (int e = 0; e < 4; e++) acc[mt][nt][e] = 0.0f;

    // ---- gate chunks 0,1 then prefetch counter for chunk 2 ----
    int pref_val = 0;
    if (tid == 0) {
        while (ld_acquire(&g_done[0]) < UNITS_PER_CHUNK) __nanosleep(64);
        while (ld_acquire(&g_done[1]) < UNITS_PER_CHUNK) __nanosleep(64);
        pref_val = ld_acquire(&g_done[2]);
    }
    __syncthreads();

    // ---- prologue: prefetch stages 0..1 ----
    #pragma unroll
    for (int p = 0; p < STAGES - 1; p++) {
        const uint32_t sA = sb + p * STAGE_BYTES;
        const uint32_t sB = sA + A_STAGE_BYTES;
        const int k0 = p * TILE_K;
        #pragma unroll
        for (int i = 0; i < 4; i++)
            CP_ASYNC16(sA + (i * 32 + ld_row) * 128 + sw_off,
                       gA + (size_t)i * 32 * K_TOTAL + k0);
        #pragma unroll
        for (int i = 0; i < 4; i++)
            CP_ASYNC16(sB + (i * 32 + ld_row) * 128 + sw_off,
                       gB + (size_t)i * 32 * K_TOTAL + k0);
        CP_COMMIT();
    }

    // ---- mainloop (compute-first, interleaved copies, pipelined gate) ----
    int buf = 0;
    int nbuf = STAGES - 1;
    for (int kt = 0; kt < NITER; kt++) {
        CP_WAIT();         // stage kt arrived (this thread)
        if (tid == 0) {
            const int need = kt + STAGES - 1;   // chunk consumed by this iter's copies
            if (need < NITER) {
                // pref_val was loaded one full iteration ago -> usually ready
                while (pref_val < UNITS_PER_CHUNK) {
                    __nanosleep(32);
                    pref_val = ld_acquire(&g_done[need]);
                }
                pref_val = (need + 1 < NITER) ? ld_acquire(&g_done[need + 1])
                                              : UNITS_PER_CHUNK;
            }
        }
        __syncthreads();   // publish copies + broadcast gate

        const uint32_t sA = sb + buf * STAGE_BYTES;
        const uint32_t sB = sA + A_STAGE_BYTES;
        const uint32_t aBase = sA + a_row * 128;
        const uint32_t bBase = sB + b_row * 128;

        const uint32_t pA = sb + nbuf * STAGE_BYTES;
        const uint32_t pB = pA + A_STAGE_BYTES;
        const int kpref = (kt + STAGES - 1 < NITER) ? (kt + STAGES - 1) * TILE_K : 0;

        uint32_t b_frag[2][4][2];
        {
            const uint32_t boff = (uint32_t)((kc_b ^ s7) << 4);
            #pragma unroll
            for (int j = 0; j < 2; j++)
                LDMATRIX_X4(b_frag[0][2 * j][0], b_frag[0][2 * j][1],
                            b_frag[0][2 * j + 1][0], b_frag[0][2 * j + 1][1],
                            bBase + j * 2048 + boff);
        }

        #pragma unroll
        for (int ks = 0; ks < 4; ks++) {
            const int cur = ks & 1;
            const int nxt = cur ^ 1;
            uint32_t a_frag[4][4];
            const uint32_t aoff = (uint32_t)(((ks * 2 + kc_a) ^ s7) << 4);
            #pragma unroll
            for (int mt = 0; mt < 4; mt++)
                LDMATRIX_X4(a_frag[mt][0], a_frag[mt][1], a_frag[mt][2], a_frag[mt][3],
                            aBase + mt * 2048 + aoff);
            if (ks < 3) {
                const uint32_t boff = (uint32_t)((((ks + 1) * 2 + kc_b) ^ s7) << 4);
                #pragma unroll
                for (int j = 0; j < 2; j++)
                    LDMATRIX_X4(b_frag[nxt][2 * j][0], b_frag[nxt][2 * j][1],
                                b_frag[nxt][2 * j + 1][0], b_frag[nxt][2 * j + 1][1],
                                bBase + j * 2048 + boff);
            }
            #pragma unroll
            for (int mt = 0; mt < 4; mt++)
                #pragma unroll
                for (int nt = 0; nt < 4; nt++)
                    mma16816(acc[mt][nt], a_frag[mt], b_frag[cur][nt]);

            // 2 of the 8 stage-(kt+2) copies in the MMA shadow
            #pragma unroll
            for (int t = 0; t < 2; t++) {
                const int i = ks * 2 + t;
                if (i < 4)
                    CP_ASYNC16(pA + (i * 32 + ld_row) * 128 + sw_off,
                               gA + (size_t)i * 32 * K_TOTAL + kpref);
                else
                    CP_ASYNC16(pB + ((i - 4) * 32 + ld_row) * 128 + sw_off,
                               gB + (size_t)(i - 4) * 32 * K_TOTAL + kpref);
            }
        }
        CP_COMMIT();

        buf = (buf + 1 == STAGES) ? 0 : buf + 1;
        nbuf = (nbuf + 1 == STAGES) ? 0 : nbuf + 1;
    }

    // ---- epilogue ----
    const float sw = __ldg(scale_w_p);
    const int mrow = m0 + warp_m * 64 + (lid >> 2);
    const int ncol = n0 + warp_n * 32 + (lid & 3) * 2;

    #pragma unroll
    for (int mt = 0; mt < 4; mt++) {
        #pragma unroll
        for (int nt = 0; nt < 4; nt++) {
            const int m1 = mrow + mt * 16;
            const int n1 = ncol + nt * 8;
            const float b0 = g_bias[n1];
            const float b1 = g_bias[n1 + 1];
            float2 v0 = make_float2(fmaf(sw, acc[mt][nt][0], b0),
                                    fmaf(sw, acc[mt][nt][1], b1));
            float2 v1 = make_float2(fmaf(sw, acc[mt][nt][2], b0),
                                    fmaf(sw, acc[mt][nt][3], b1));
            __stcs(reinterpret_cast<float2*>(out + (size_t)m1 * N_TOTAL + n1), v0);
            __stcs(reinterpret_cast<float2*>(out + (size_t)(m1 + 8) * N_TOTAL + n1), v1);
        }
    }
}

// ============================================================================
// Host
// ============================================================================
extern "C" void kernel_launch(void* const* d_in, const int* in_sizes, int n_in,
                              void* d_out, int out_size) {
    const float* x   = (const float*)d_in[0];
    const int* pw    = (const int*)d_in[1];
    const int* pb    = (const int*)d_in[2];
    const float* sw  = (const float*)d_in[3];
    const float* sbp = (const float*)d_in[4];
    float* out = (float*)d_out;

    // Reset completion counters (graph-legal async memset node)
    void* done_ptr = nullptr;
    cudaGetSymbolAddress(&done_ptr, g_done);
    cudaMemsetAsync(done_ptr, 0, sizeof(int) * NITER);

    cudaFuncSetAttribute(fused_kernel, cudaFuncAttributeMaxDynamicSharedMemorySize, SMEM_TOTAL);
    const int nblocks = PRE_CTAS + (M_TOTAL / TILE_M) * (N_TOTAL / TILE_N);   // 64 + 2048
    fused_kernel<<<nblocks, 256, SMEM_TOTAL>>>(out, x, pw, pb, sw, sbp);
}

// round 13
// speedup vs baseline: 1.0719x; 1.0719x over previous
#include <cuda_runtime.h>
#include <cuda_fp16.h>
#include <cstdint>
#include <cstddef>

// ============================================================================
// Problem constants
// ============================================================================
#define M_TOTAL 8192
#define N_TOTAL 4096
#define K_TOTAL 4096

#define TILE_M 128
#define TILE_N 128
#define TILE_K 64            // fp16 elems per stage row-chunk (128 bytes)
#define STAGES 3             // 96KB -> two CTAs per SM
#define NITER (K_TOTAL / TILE_K)   // 64

#define A_STAGE_BYTES (TILE_M * 128)          // 16384
#define B_STAGE_BYTES (TILE_N * 128)          // 16384
#define STAGE_BYTES (A_STAGE_BYTES + B_STAGE_BYTES)   // 32768
#define SMEM_TOTAL (STAGES * STAGE_BYTES)             // 98304

// ============================================================================
// Device scratch (allocation-free: __device__ globals)
// ============================================================================
__device__ __half g_xh[(size_t)M_TOTAL * K_TOTAL];   // 64 MB  x in fp16, [M,K]
__device__ __half g_wh[(size_t)N_TOTAL * K_TOTAL];   // 32 MB  unpacked q in fp16, [N,K]
__device__ float  g_bias[N_TOTAL];

// ============================================================================
// PTX helpers (baseline sm_103 target — NO 'a'-suffix features)
// ============================================================================
__device__ __forceinline__ uint32_t smem_u32(const void* p) {
    uint32_t a;
    asm("{ .reg .u64 t; cvta.to.shared.u64 t, %1; cvt.u32.u64 %0, t; }" : "=r"(a) : "l"(p));
    return a;
}

#define CP_ASYNC16(smem, gmem) \
    asm volatile("cp.async.cg.shared.global [%0], [%1], 16;" \
                 :: "r"(smem), "l"(gmem) : "memory")
#define CP_COMMIT() asm volatile("cp.async.commit_group;" ::: "memory")
#define CP_WAIT()   asm volatile("cp.async.wait_group %0;" :: "n"(STAGES - 2) : "memory")

#define LDMATRIX_X4(r0, r1, r2, r3, addr) \
    asm volatile("ldmatrix.sync.aligned.m8n8.x4.shared.b16 {%0,%1,%2,%3}, [%4];" \
                 : "=r"(r0), "=r"(r1), "=r"(r2), "=r"(r3) : "r"(addr))

__device__ __forceinline__ void mma16816(float* c, const uint32_t* a, const uint32_t* b) {
    asm volatile(
        "mma.sync.aligned.m16n8k16.row.col.f32.f16.f16.f32 "
        "{%0,%1,%2,%3}, {%4,%5,%6,%7}, {%8,%9}, {%0,%1,%2,%3};"
        : "+f"(c[0]), "+f"(c[1]), "+f"(c[2]), "+f"(c[3])
        : "r"(a[0]), "r"(a[1]), "r"(a[2]), "r"(a[3]), "r"(b[0]), "r"(b[1]));
}

// ============================================================================
// Pre-pass: wide-vector version. Thread i:
//   x:  4 float4 loads (64B)  -> 2 uint4 stores to g_xh (32B)
//   pw: 1 int4 load (16B = 4 packed bytes) -> 1 uint4 store to g_wh (16B)
// MLP 8 loads/thread (round-7 profile: DRAM 70%, issue 12% -> load-issue bound)
// ============================================================================
__global__ void prepass_kernel(const float* __restrict__ x,
                               const int* __restrict__ pw,
                               const int* __restrict__ pb,
                               const float* __restrict__ scale_b) {
    const int i = blockIdx.x * blockDim.x + threadIdx.x;   // 0 .. 2097151

    // ---- x: 4 float4 -> 16 halves ----
    const float4* xv = reinterpret_cast<const float4*>(x) + (size_t)i * 4;
    float4 v0 = xv[0], v1 = xv[1], v2 = xv[2], v3 = xv[3];
    uint4 o0, o1;
    {
        __half2 h;
        h = __floats2half2_rn(v0.x, v0.y); o0.x = *reinterpret_cast<unsigned*>(&h);
        h = __floats2half2_rn(v0.z, v0.w); o0.y = *reinterpret_cast<unsigned*>(&h);
        h = __floats2half2_rn(v1.x, v1.y); o0.z = *reinterpret_cast<unsigned*>(&h);
        h = __floats2half2_rn(v1.z, v1.w); o0.w = *reinterpret_cast<unsigned*>(&h);
        h = __floats2half2_rn(v2.x, v2.y); o1.x = *reinterpret_cast<unsigned*>(&h);
        h = __floats2half2_rn(v2.z, v2.w); o1.y = *reinterpret_cast<unsigned*>(&h);
        h = __floats2half2_rn(v3.x, v3.y); o1.z = *reinterpret_cast<unsigned*>(&h);
        h = __floats2half2_rn(v3.z, v3.w); o1.w = *reinterpret_cast<unsigned*>(&h);
    }
    reinterpret_cast<uint4*>(g_xh)[(size_t)i * 2]     = o0;
    reinterpret_cast<uint4*>(g_xh)[(size_t)i * 2 + 1] = o1;

    // ---- w: int4 (4 packed bytes) -> 8 halves ----
    int4 p = reinterpret_cast<const int4*>(pw)[i];
    uint4 w;
    {
        __half2 h;
        h = __halves2half2(__int2half_rn(((p.x >> 4) & 15) - 8),
                           __int2half_rn((p.x & 15) - 8));
        w.x = *reinterpret_cast<unsigned*>(&h);
        h = __halves2half2(__int2half_rn(((p.y >> 4) & 15) - 8),
                           __int2half_rn((p.y & 15) - 8));
        w.y = *reinterpret_cast<unsigned*>(&h);
        h = __halves2half2(__int2half_rn(((p.z >> 4) & 15) - 8),
                           __int2half_rn((p.z & 15) - 8));
        w.z = *reinterpret_cast<unsigned*>(&h);
        h = __halves2half2(__int2half_rn(((p.w >> 4) & 15) - 8),
                           __int2half_rn((p.w & 15) - 8));
        w.w = *reinterpret_cast<unsigned*>(&h);
    }
    reinterpret_cast<uint4*>(g_wh)[i] = w;

    // ---- bias ----
    if (i < N_TOTAL / 2) {
        float sb = *scale_b;
        int bb = pb[i];
        g_bias[2 * i]     = sb * (float)(((bb >> 4) & 15) - 8);
        g_bias[2 * i + 1] = sb * (float)((bb & 15) - 8);
    }
}

// ============================================================================
// GEMM (round-9 winner, verbatim): 256 threads, CTA 128x128, warp 64x32,
// 2 CTAs/SM, 3 stages, single barrier, compute-first with copies interleaved
// into the ks loop, B-frag double-buffer.
// ============================================================================
__global__ void __launch_bounds__(256, 2) gemm_kernel(
    float* __restrict__ out, const float* __restrict__ scale_w_p)
{
    extern __shared__ __align__(1024) char smem[];
    const uint32_t sb = smem_u32(smem);

    const int tid = threadIdx.x;
    const int wid = tid >> 5;
    const int lid = tid & 31;
    const int warp_m = wid & 1;   // 0..1
    const int warp_n = wid >> 1;  // 0..3

    const int m0 = blockIdx.y * TILE_M;
    const int n0 = blockIdx.x * TILE_N;

    const int ld_row = tid >> 3;          // 0..31 row-subgroup
    const int ld_chk = tid & 7;           // 0..7  16B column chunk
    const __half* gA = g_xh + (size_t)(m0 + ld_row) * K_TOTAL + ld_chk * 8;
    const __half* gB = g_wh + (size_t)(n0 + ld_row) * K_TOTAL + ld_chk * 8;
    const uint32_t sw_off = (uint32_t)((ld_chk ^ (ld_row & 7)) << 4);

    const int s7 = lid & 7;               // swizzle xor term (row & 7 invariant)
    const int q  = lid >> 3;              // 0..3
    const int a_row = warp_m * 64 + ((q & 1) << 3) + s7;
    const int kc_a = q >> 1;
    const int b_row = warp_n * 32 + ((q >> 1) << 3) + s7;
    const int kc_b = q & 1;

    float acc[4][4][4];
    #pragma unroll
    for (int mt = 0; mt < 4; mt++)
        #pragma unroll
        for (int nt = 0; nt < 4; nt++)
            #pragma unroll
            for (int e = 0; e < 4; e++) acc[mt][nt][e] = 0.0f;

    // ---- prologue: prefetch stages 0..1 ----
    #pragma unroll
    for (int p = 0; p < STAGES - 1; p++) {
        const uint32_t sA = sb + p * STAGE_BYTES;
        const uint32_t sB = sA + A_STAGE_BYTES;
        const int k0 = p * TILE_K;
        #pragma unroll
        for (int i = 0; i < 4; i++)
            CP_ASYNC16(sA + (i * 32 + ld_row) * 128 + sw_off,
                       gA + (size_t)i * 32 * K_TOTAL + k0);
        #pragma unroll
        for (int i = 0; i < 4; i++)
            CP_ASYNC16(sB + (i * 32 + ld_row) * 128 + sw_off,
                       gB + (size_t)i * 32 * K_TOTAL + k0);
        CP_COMMIT();
    }

    // ---- mainloop (compute-first, copies interleaved into ks loop) ----
    int buf = 0;
    int nbuf = STAGES - 1;
    for (int kt = 0; kt < NITER; kt++) {
        CP_WAIT();         // stage kt arrived (this thread)
        __syncthreads();   // publish; nobody still reads nbuf

        const uint32_t sA = sb + buf * STAGE_BYTES;
        const uint32_t sB = sA + A_STAGE_BYTES;
        const uint32_t aBase = sA + a_row * 128;
        const uint32_t bBase = sB + b_row * 128;

        const uint32_t pA = sb + nbuf * STAGE_BYTES;
        const uint32_t pB = pA + A_STAGE_BYTES;
        const int kpref = (kt + STAGES - 1 < NITER) ? (kt + STAGES - 1) * TILE_K : 0;

        uint32_t b_frag[2][4][2];
        {
            const uint32_t boff = (uint32_t)((kc_b ^ s7) << 4);
            #pragma unroll
            for (int j = 0; j < 2; j++)
                LDMATRIX_X4(b_frag[0][2 * j][0], b_frag[0][2 * j][1],
                            b_frag[0][2 * j + 1][0], b_frag[0][2 * j + 1][1],
                            bBase + j * 2048 + boff);
        }

        #pragma unroll
        for (int ks = 0; ks < 4; ks++) {
            const int cur = ks & 1;
            const int nxt = cur ^ 1;
            uint32_t a_frag[4][4];
            const uint32_t aoff = (uint32_t)(((ks * 2 + kc_a) ^ s7) << 4);
            #pragma unroll
            for (int mt = 0; mt < 4; mt++)
                LDMATRIX_X4(a_frag[mt][0], a_frag[mt][1], a_frag[mt][2], a_frag[mt][3],
                            aBase + mt * 2048 + aoff);
            if (ks < 3) {   // prefetch B(ks+1)
                const uint32_t boff = (uint32_t)((((ks + 1) * 2 + kc_b) ^ s7) << 4);
                #pragma unroll
                for (int j = 0; j < 2; j++)
                    LDMATRIX_X4(b_frag[nxt][2 * j][0], b_frag[nxt][2 * j][1],
                                b_frag[nxt][2 * j + 1][0], b_frag[nxt][2 * j + 1][1],
                                bBase + j * 2048 + boff);
            }
            #pragma unroll
            for (int mt = 0; mt < 4; mt++)
                #pragma unroll
                for (int nt = 0; nt < 4; nt++)
                    mma16816(acc[mt][nt], a_frag[mt], b_frag[cur][nt]);

            // 2 of the 8 stage-(kt+2) copies, in the shadow of this MMA block
            #pragma unroll
            for (int t = 0; t < 2; t++) {
                const int i = ks * 2 + t;       // 0..7 compile-time
                if (i < 4)
                    CP_ASYNC16(pA + (i * 32 + ld_row) * 128 + sw_off,
                               gA + (size_t)i * 32 * K_TOTAL + kpref);
                else
                    CP_ASYNC16(pB + ((i - 4) * 32 + ld_row) * 128 + sw_off,
                               gB + (size_t)(i - 4) * 32 * K_TOTAL + kpref);
            }
        }
        CP_COMMIT();       // one group per iteration

        buf = (buf + 1 == STAGES) ? 0 : buf + 1;
        nbuf = (nbuf + 1 == STAGES) ? 0 : nbuf + 1;
    }

    // ---- epilogue ----
    const float sw = __ldg(scale_w_p);
    const int mrow = m0 + warp_m * 64 + (lid >> 2);
    const int ncol = n0 + warp_n * 32 + (lid & 3) * 2;

    #pragma unroll
    for (int mt = 0; mt < 4; mt++) {
        #pragma unroll
        for (int nt = 0; nt < 4; nt++) {
            const int m1 = mrow + mt * 16;
            const int n1 = ncol + nt * 8;
            const float b0 = g_bias[n1];
            const float b1 = g_bias[n1 + 1];
            float2 v0 = make_float2(fmaf(sw, acc[mt][nt][0], b0),
                                    fmaf(sw, acc[mt][nt][1], b1));
            float2 v1 = make_float2(fmaf(sw, acc[mt][nt][2], b0),
                                    fmaf(sw, acc[mt][nt][3], b1));
            __stcs(reinterpret_cast<float2*>(out + (size_t)m1 * N_TOTAL + n1), v0);
            __stcs(reinterpret_cast<float2*>(out + (size_t)(m1 + 8) * N_TOTAL + n1), v1);
        }
    }
}

// ============================================================================
// Host
// ============================================================================
extern "C" void kernel_launch(void* const* d_in, const int* in_sizes, int n_in,
                              void* d_out, int out_size) {
    const float* x   = (const float*)d_in[0];
    const int* pw    = (const int*)d_in[1];
    const int* pb    = (const int*)d_in[2];
    const float* sw  = (const float*)d_in[3];
    const float* sbp = (const float*)d_in[4];
    float* out = (float*)d_out;

    // 2.097M threads: each converts 16 x-floats + 4 packed-w bytes
    prepass_kernel<<<(M_TOTAL * K_TOTAL / 16) / 256, 256>>>(x, pw, pb, sbp);

    cudaFuncSetAttribute(gemm_kernel, cudaFuncAttributeMaxDynamicSharedMemorySize, SMEM_TOTAL);
    dim3 grid(N_TOTAL / TILE_N, M_TOTAL / TILE_M);   // (32, 64)
    gemm_kernel<<<grid, 256, SMEM_TOTAL>>>(out, sw);
}